// round 3
// baseline (speedup 1.0000x reference)
#include <cuda_runtime.h>
#include <math.h>

#define T_Q 2048
#define T_K 2048
#define BATCH 4
#define EMB 1024
#define NHEADS 16
#define HDIM 64
#define MROWS (T_Q * BATCH)   // 8192
#define NEGINF -1e9f
#define NMASK (BATCH * T_K)   // 8192

// Scratch (static device globals: allocation inside kernel_launch is forbidden)
__device__ float g_Q[MROWS * EMB];
__device__ float g_K[MROWS * EMB];
__device__ float g_V[MROWS * EMB];
__device__ float g_AO[MROWS * EMB];
__device__ unsigned char g_mask[NMASK];
__device__ int g_mask_kind;

// ---------------------------------------------------------------------------
// Mask dtype sniff + normalization.
// The reference mask is jnp.bool_; the harness may serialize it as bool(1B),
// int32, or float32. Inspect the first NMASK bytes (in-bounds for every
// candidate dtype) and classify:
//   - all bytes at idx%4!=0 zero            -> int32 (0/1 LE ints)
//   - else all bytes at idx%4==0 zero       -> float32 (1.0f = 00 00 80 3F)
//   - else                                  -> uint8 bool
// ---------------------------------------------------------------------------
__global__ void sniff_mask_kernel(const unsigned char* __restrict__ m)
{
    __shared__ int nz_off, nz_al;
    if (threadIdx.x == 0) { nz_off = 0; nz_al = 0; }
    __syncthreads();
    int loc_off = 0, loc_al = 0;
    for (int i = threadIdx.x; i < NMASK; i += blockDim.x) {
        unsigned char v = m[i];
        if (v) { if (i & 3) loc_off = 1; else loc_al = 1; }
    }
    if (loc_off) atomicOr(&nz_off, 1);
    if (loc_al)  atomicOr(&nz_al, 1);
    __syncthreads();
    if (threadIdx.x == 0) {
        int kind;
        if (!nz_off)     kind = 1;  // int32
        else if (!nz_al) kind = 2;  // float32
        else             kind = 0;  // uint8 / bool
        g_mask_kind = kind;
    }
}

__global__ void norm_mask_kernel(const void* __restrict__ m)
{
    int i = blockIdx.x * blockDim.x + threadIdx.x;
    if (i >= NMASK) return;
    int kind = g_mask_kind;
    unsigned char r;
    if (kind == 1)      r = (((const int*)m)[i]   != 0);
    else if (kind == 2) r = (((const float*)m)[i] != 0.f);
    else                r = (((const unsigned char*)m)[i] != 0);
    g_mask[i] = r;
}

// ---------------------------------------------------------------------------
// SGEMM NT:  C[M,N] = A[M,K] * B[N,K]^T   (both A and B row-major, K-contig)
// 128x128 block tile, BK=16, 256 threads, 8x8 per thread.
// ---------------------------------------------------------------------------
#define BM 128
#define BN 128
#define BKD 16

__global__ __launch_bounds__(256) void sgemm_nt(const float* __restrict__ A,
                                                const float* __restrict__ B,
                                                float* __restrict__ C,
                                                int M, int N, int K)
{
    __shared__ float As[BKD][BM];
    __shared__ float Bs[BKD][BN];

    const int tid = threadIdx.x;
    const int tx  = tid & 15;      // 0..15 -> N direction
    const int ty  = tid >> 4;      // 0..15 -> M direction
    const int lrow = tid >> 2;          // 0..63
    const int lcol = (tid & 3) << 2;    // 0,4,8,12

    const float* Ab = A + (size_t)blockIdx.y * BM * K;
    const float* Bb = B + (size_t)blockIdx.x * BN * K;

    float acc[8][8];
#pragma unroll
    for (int i = 0; i < 8; i++)
#pragma unroll
        for (int j = 0; j < 8; j++) acc[i][j] = 0.f;

    for (int kt = 0; kt < K; kt += BKD) {
#pragma unroll
        for (int p = 0; p < 2; p++) {
            int r = lrow + p * 64;
            float4 va = *(const float4*)(Ab + (size_t)r * K + kt + lcol);
            As[lcol + 0][r] = va.x;
            As[lcol + 1][r] = va.y;
            As[lcol + 2][r] = va.z;
            As[lcol + 3][r] = va.w;
            float4 vb = *(const float4*)(Bb + (size_t)r * K + kt + lcol);
            Bs[lcol + 0][r] = vb.x;
            Bs[lcol + 1][r] = vb.y;
            Bs[lcol + 2][r] = vb.z;
            Bs[lcol + 3][r] = vb.w;
        }
        __syncthreads();

#pragma unroll
        for (int kk = 0; kk < BKD; kk++) {
            float4 a0 = *(const float4*)(&As[kk][ty * 8]);
            float4 a1 = *(const float4*)(&As[kk][ty * 8 + 4]);
            float4 b0 = *(const float4*)(&Bs[kk][tx * 8]);
            float4 b1 = *(const float4*)(&Bs[kk][tx * 8 + 4]);
            float ra[8] = {a0.x, a0.y, a0.z, a0.w, a1.x, a1.y, a1.z, a1.w};
            float rb[8] = {b0.x, b0.y, b0.z, b0.w, b1.x, b1.y, b1.z, b1.w};
#pragma unroll
            for (int i = 0; i < 8; i++)
#pragma unroll
                for (int j = 0; j < 8; j++)
                    acc[i][j] = fmaf(ra[i], rb[j], acc[i][j]);
        }
        __syncthreads();
    }

#pragma unroll
    for (int i = 0; i < 8; i++) {
        size_t row = (size_t)blockIdx.y * BM + ty * 8 + i;
        float* cp = C + row * N + blockIdx.x * BN + tx * 8;
        float4 o0 = make_float4(acc[i][0], acc[i][1], acc[i][2], acc[i][3]);
        float4 o1 = make_float4(acc[i][4], acc[i][5], acc[i][6], acc[i][7]);
        *(float4*)(cp)     = o0;
        *(float4*)(cp + 4) = o1;
    }
}

// ---------------------------------------------------------------------------
// Flash attention (fp32): per block one (b, h, 64-query tile).
// Tiles of 64 keys, online softmax. Smem tiles transposed w/ stride 65
// (odd stride -> conflict-free column access).
// ---------------------------------------------------------------------------
struct AttnSmem {
    float Qt[HDIM][65];   // Qt[d][q]
    float Kt[HDIM][65];   // Kt[d][k]
    float Vs[64][65];     // Vs[k][d]
    float Pt[64][65];     // Pt[k][q]  (scores, then probabilities)
    float m[64];
    float l[64];
    float alpha[64];
    unsigned char msk[64];
};

extern __shared__ char s_raw[];

__global__ __launch_bounds__(256) void attn_kernel(const float* __restrict__ Qg,
                                                   const float* __restrict__ Kg,
                                                   const float* __restrict__ Vg,
                                                   const unsigned char* __restrict__ mask,
                                                   float* __restrict__ Og)
{
    AttnSmem& s = *reinterpret_cast<AttnSmem*>(s_raw);
    const int b  = blockIdx.z;
    const int h  = blockIdx.y;
    const int qt = blockIdx.x;
    const int tid = threadIdx.x;
    const int tx = tid & 15;   // 0..15
    const int ty = tid >> 4;   // 0..15
    const int warp = tid >> 5;
    const int lane = tid & 31;
    const size_t headoff = (size_t)h * HDIM;

    if (tid < 64) { s.m[tid] = -INFINITY; s.l[tid] = 0.f; }

    // Load Q tile transposed: Qt[d][q]
    for (int idx = tid; idx < 64 * 16; idx += 256) {
        int r  = idx >> 4;
        int c4 = (idx & 15) << 2;
        int tg = qt * 64 + r;
        float4 v = *(const float4*)(Qg + ((size_t)tg * BATCH + b) * EMB + headoff + c4);
        s.Qt[c4 + 0][r] = v.x;
        s.Qt[c4 + 1][r] = v.y;
        s.Qt[c4 + 2][r] = v.z;
        s.Qt[c4 + 3][r] = v.w;
    }

    float acc[4][4];
#pragma unroll
    for (int i = 0; i < 4; i++)
#pragma unroll
        for (int j = 0; j < 4; j++) acc[i][j] = 0.f;

    for (int kt = 0; kt < T_K / 64; kt++) {
        __syncthreads();   // previous iter's consumers done; Q load done (iter 0)

        // Load K (transposed), V (natural), mask
        for (int idx = tid; idx < 64 * 16; idx += 256) {
            int r  = idx >> 4;
            int c4 = (idx & 15) << 2;
            int kg = kt * 64 + r;
            size_t base = ((size_t)kg * BATCH + b) * EMB + headoff + c4;
            float4 vk = *(const float4*)(Kg + base);
            s.Kt[c4 + 0][r] = vk.x;
            s.Kt[c4 + 1][r] = vk.y;
            s.Kt[c4 + 2][r] = vk.z;
            s.Kt[c4 + 3][r] = vk.w;
            float4 vv = *(const float4*)(Vg + base);
            s.Vs[r][c4 + 0] = vv.x;
            s.Vs[r][c4 + 1] = vv.y;
            s.Vs[r][c4 + 2] = vv.z;
            s.Vs[r][c4 + 3] = vv.w;
        }
        if (tid < 64) s.msk[tid] = mask[(size_t)b * T_K + kt * 64 + tid];
        __syncthreads();

        // ---- S = Q K^T (thread computes 4q x 4k) ----
        float sacc[4][4];
#pragma unroll
        for (int i = 0; i < 4; i++)
#pragma unroll
            for (int j = 0; j < 4; j++) sacc[i][j] = 0.f;

#pragma unroll 8
        for (int dd = 0; dd < HDIM; dd++) {
            float ra[4], rb[4];
#pragma unroll
            for (int i = 0; i < 4; i++) ra[i] = s.Qt[dd][ty * 4 + i];
#pragma unroll
            for (int j = 0; j < 4; j++) rb[j] = s.Kt[dd][tx * 4 + j];
#pragma unroll
            for (int i = 0; i < 4; i++)
#pragma unroll
                for (int j = 0; j < 4; j++)
                    sacc[i][j] = fmaf(ra[i], rb[j], sacc[i][j]);
        }
        // write masked + scaled scores to Pt[k][q]
#pragma unroll
        for (int j = 0; j < 4; j++) {
            int k = tx * 4 + j;
            bool msk = s.msk[k] != 0;
#pragma unroll
            for (int i = 0; i < 4; i++) {
                float v = msk ? NEGINF : sacc[i][j] * 0.125f;
                s.Pt[k][ty * 4 + i] = v;
            }
        }
        __syncthreads();

        // ---- online softmax: warp w owns rows w*8 .. w*8+7 ----
        for (int r = 0; r < 8; r++) {
            int q = warp * 8 + r;
            float s0 = s.Pt[lane][q];
            float s1 = s.Pt[lane + 32][q];
            float tmax = fmaxf(s0, s1);
#pragma unroll
            for (int off = 16; off > 0; off >>= 1)
                tmax = fmaxf(tmax, __shfl_xor_sync(0xffffffffu, tmax, off));
            float mold = s.m[q];
            float mnew = fmaxf(mold, tmax);
            float p0 = __expf(s0 - mnew);
            float p1 = __expf(s1 - mnew);
            s.Pt[lane][q]      = p0;
            s.Pt[lane + 32][q] = p1;
            float ps = p0 + p1;
#pragma unroll
            for (int off = 16; off > 0; off >>= 1)
                ps += __shfl_xor_sync(0xffffffffu, ps, off);
            if (lane == 0) {
                float al = __expf(mold - mnew);
                s.alpha[q] = al;
                s.l[q] = s.l[q] * al + ps;
                s.m[q] = mnew;
            }
        }
        __syncthreads();

        // ---- O = O*alpha + P V  (thread: 4q x 4d) ----
        float al[4];
#pragma unroll
        for (int i = 0; i < 4; i++) al[i] = s.alpha[ty * 4 + i];
#pragma unroll
        for (int i = 0; i < 4; i++)
#pragma unroll
            for (int j = 0; j < 4; j++) acc[i][j] *= al[i];

#pragma unroll 8
        for (int kk = 0; kk < 64; kk++) {
            float ra[4], rb[4];
#pragma unroll
            for (int i = 0; i < 4; i++) ra[i] = s.Pt[kk][ty * 4 + i];
#pragma unroll
            for (int j = 0; j < 4; j++) rb[j] = s.Vs[kk][tx * 4 + j];
#pragma unroll
            for (int i = 0; i < 4; i++)
#pragma unroll
                for (int j = 0; j < 4; j++)
                    acc[i][j] = fmaf(ra[i], rb[j], acc[i][j]);
        }
    }

    // final: divide by l, write to (t, b, e) layout
#pragma unroll
    for (int i = 0; i < 4; i++) {
        int q = ty * 4 + i;
        float inv = 1.f / s.l[q];
        int tg = qt * 64 + q;
        float* op = Og + ((size_t)tg * BATCH + b) * EMB + headoff + tx * 4;
#pragma unroll
        for (int j = 0; j < 4; j++) op[j] = acc[i][j] * inv;
    }
}

// ---------------------------------------------------------------------------
// Launch: mask normalize -> Q/K/V projections -> attention -> output proj
// Inputs: 0=q 1=k 2=v 3=key_padding_mask 4=Wq 5=Wk 6=Wv 7=Wo
// ---------------------------------------------------------------------------
extern "C" void kernel_launch(void* const* d_in, const int* in_sizes, int n_in,
                              void* d_out, int out_size)
{
    const float* q  = (const float*)d_in[0];
    const float* k  = (const float*)d_in[1];
    const float* v  = (const float*)d_in[2];
    const void*  maskraw = d_in[3];
    const float* Wq = (const float*)d_in[4];
    const float* Wk = (const float*)d_in[5];
    const float* Wv = (const float*)d_in[6];
    const float* Wo = (const float*)d_in[7];
    float* out = (float*)d_out;

    float *gq, *gk, *gv, *gao;
    unsigned char* gmask;
    cudaGetSymbolAddress((void**)&gq,  g_Q);
    cudaGetSymbolAddress((void**)&gk,  g_K);
    cudaGetSymbolAddress((void**)&gv,  g_V);
    cudaGetSymbolAddress((void**)&gao, g_AO);
    cudaGetSymbolAddress((void**)&gmask, g_mask);

    const int attn_smem = (int)sizeof(AttnSmem);
    cudaFuncSetAttribute(attn_kernel, cudaFuncAttributeMaxDynamicSharedMemorySize,
                         attn_smem);

    // Mask dtype sniff + canonicalize to uint8
    sniff_mask_kernel<<<1, 256>>>((const unsigned char*)maskraw);
    norm_mask_kernel<<<NMASK / 256, 256>>>(maskraw);

    dim3 ggrid(EMB / BN, MROWS / BM);   // (8, 64)
    sgemm_nt<<<ggrid, 256>>>(q, Wq, gq, MROWS, EMB, EMB);
    sgemm_nt<<<ggrid, 256>>>(k, Wk, gk, MROWS, EMB, EMB);
    sgemm_nt<<<ggrid, 256>>>(v, Wv, gv, MROWS, EMB, EMB);

    dim3 agrid(T_Q / 64, NHEADS, BATCH);  // (32, 16, 4)
    attn_kernel<<<agrid, 256, attn_smem>>>(gq, gk, gv, gmask, gao);

    sgemm_nt<<<ggrid, 256>>>(gao, Wo, out, MROWS, EMB, EMB);
}

// round 5
// speedup vs baseline: 1.9040x; 1.9040x over previous
#include <cuda_runtime.h>
#include <cuda_bf16.h>
#include <math.h>
#include <stdint.h>

#define T_Q 2048
#define T_K 2048
#define BATCH 4
#define EMB 1024
#define NHEADS 16
#define HDIM 64
#define MROWS (T_Q * BATCH)   // 8192
#define NEGINF -1e9f
#define NMASK (BATCH * T_K)   // 8192

// Scratch (static device globals: allocation inside kernel_launch is forbidden)
__device__ float g_Q[MROWS * EMB];
__device__ float g_K[MROWS * EMB];
__device__ float g_V[MROWS * EMB];
__device__ float g_AO[MROWS * EMB];
__device__ unsigned char g_mask[NMASK];
__device__ int g_mask_kind;

// ===========================================================================
// helpers
// ===========================================================================
__device__ __forceinline__ uint32_t smem_u32(const void* p) {
    uint32_t a;
    asm("{ .reg .u64 t; cvta.to.shared.u64 t, %1; cvt.u32.u64 %0, t; }"
        : "=r"(a) : "l"(p));
    return a;
}

// mma.sync m16n8k16 row.col bf16 -> f32 accumulate (in place)
__device__ __forceinline__ void mma16816(float* c, const uint32_t* a,
                                         uint32_t b0, uint32_t b1) {
    asm volatile(
        "mma.sync.aligned.m16n8k16.row.col.f32.bf16.bf16.f32 "
        "{%0,%1,%2,%3}, {%4,%5,%6,%7}, {%8,%9}, {%0,%1,%2,%3};"
        : "+f"(c[0]), "+f"(c[1]), "+f"(c[2]), "+f"(c[3])
        : "r"(a[0]), "r"(a[1]), "r"(a[2]), "r"(a[3]), "r"(b0), "r"(b1));
}

__device__ __forceinline__ void ldsm_x4(uint32_t* r, uint32_t addr) {
    asm volatile("ldmatrix.sync.aligned.m8n8.x4.shared.b16 {%0,%1,%2,%3}, [%4];"
        : "=r"(r[0]), "=r"(r[1]), "=r"(r[2]), "=r"(r[3]) : "r"(addr));
}
__device__ __forceinline__ void ldsm_x4_t(uint32_t* r, uint32_t addr) {
    asm volatile("ldmatrix.sync.aligned.m8n8.x4.trans.shared.b16 {%0,%1,%2,%3}, [%4];"
        : "=r"(r[0]), "=r"(r[1]), "=r"(r[2]), "=r"(r[3]) : "r"(addr));
}

// split fp32 -> (hi, lo) bf16
__device__ __forceinline__ void split1(float x, __nv_bfloat16& h, __nv_bfloat16& l) {
    h = __float2bfloat16(x);
    l = __float2bfloat16(x - __bfloat162float(h));
}
// split float4 into two uint2 (4 bf16 hi, 4 bf16 lo)
__device__ __forceinline__ void split4(float4 v, uint2& hw, uint2& lw) {
    __nv_bfloat16 h0, h1, h2, h3, l0, l1, l2, l3;
    split1(v.x, h0, l0); split1(v.y, h1, l1);
    split1(v.z, h2, l2); split1(v.w, h3, l3);
    hw.x = (uint32_t)__bfloat16_as_ushort(h0) | ((uint32_t)__bfloat16_as_ushort(h1) << 16);
    hw.y = (uint32_t)__bfloat16_as_ushort(h2) | ((uint32_t)__bfloat16_as_ushort(h3) << 16);
    lw.x = (uint32_t)__bfloat16_as_ushort(l0) | ((uint32_t)__bfloat16_as_ushort(l1) << 16);
    lw.y = (uint32_t)__bfloat16_as_ushort(l2) | ((uint32_t)__bfloat16_as_ushort(l3) << 16);
}

// ===========================================================================
// Mask dtype sniff + normalization (unchanged — verified in R3)
// ===========================================================================
__global__ void sniff_mask_kernel(const unsigned char* __restrict__ m)
{
    __shared__ int nz_off, nz_al;
    if (threadIdx.x == 0) { nz_off = 0; nz_al = 0; }
    __syncthreads();
    int loc_off = 0, loc_al = 0;
    for (int i = threadIdx.x; i < NMASK; i += blockDim.x) {
        unsigned char v = m[i];
        if (v) { if (i & 3) loc_off = 1; else loc_al = 1; }
    }
    if (loc_off) atomicOr(&nz_off, 1);
    if (loc_al)  atomicOr(&nz_al, 1);
    __syncthreads();
    if (threadIdx.x == 0) {
        int kind;
        if (!nz_off)     kind = 1;
        else if (!nz_al) kind = 2;
        else             kind = 0;
        g_mask_kind = kind;
    }
}

__global__ void norm_mask_kernel(const void* __restrict__ m)
{
    int i = blockIdx.x * blockDim.x + threadIdx.x;
    if (i >= NMASK) return;
    int kind = g_mask_kind;
    unsigned char r;
    if (kind == 1)      r = (((const int*)m)[i]   != 0);
    else if (kind == 2) r = (((const float*)m)[i] != 0.f);
    else                r = (((const unsigned char*)m)[i] != 0);
    g_mask[i] = r;
}

// ===========================================================================
// HMMA GEMM NT: C[M,N] = A[M,K]*B[N,K]^T, fp32 in/out, bf16 hi/lo x3 chains.
// CTA 128x128, BK=32, 256 threads, warp tile 64x32 (warp grid 2m x 4n).
// ===========================================================================
#define GBM 128
#define GBN 128
#define GBK 32
#define GSTR 40                 // bf16 row stride (pad 8)
#define G_AH 0
#define G_AL (GBM * GSTR * 2)          // 10240
#define G_BH (2 * GBM * GSTR * 2)      // 20480
#define G_BL (3 * GBM * GSTR * 2)      // 30720
#define GEMM_SMEM (4 * GBM * GSTR * 2) // 40960

extern __shared__ char sm_raw[];

__global__ __launch_bounds__(256) void gemm_mma(const float* __restrict__ A,
                                                const float* __restrict__ B,
                                                float* __restrict__ C)
{
    char* sm = sm_raw;
    uint32_t sb = smem_u32(sm);
    const int tid = threadIdx.x;
    const int wid = tid >> 5;
    const int lane = tid & 31;
    const int wm = (wid & 1) * 64;      // warp M offset
    const int wn = (wid >> 1) * 32;     // warp N offset
    const size_t rowA0 = (size_t)blockIdx.y * GBM;
    const size_t rowB0 = (size_t)blockIdx.x * GBN;

    __nv_bfloat16* Ah = (__nv_bfloat16*)(sm + G_AH);
    __nv_bfloat16* Al = (__nv_bfloat16*)(sm + G_AL);
    __nv_bfloat16* Bh = (__nv_bfloat16*)(sm + G_BH);
    __nv_bfloat16* Bl = (__nv_bfloat16*)(sm + G_BL);

    float acc[4][4][4];
#pragma unroll
    for (int mt = 0; mt < 4; mt++)
#pragma unroll
        for (int nt = 0; nt < 4; nt++)
#pragma unroll
            for (int e = 0; e < 4; e++) acc[mt][nt][e] = 0.f;

    float4 regA[4], regB[4];
    // prologue load chunk 0
#pragma unroll
    for (int t = 0; t < 4; t++) {
        int i = tid + t * 256;
        int r = i >> 3, c4 = (i & 7) << 2;
        regA[t] = *(const float4*)(A + (rowA0 + r) * EMB + c4);
        regB[t] = *(const float4*)(B + (rowB0 + r) * EMB + c4);
    }

    const int NCH = EMB / GBK;   // 32
    for (int c = 0; c < NCH; c++) {
        // stage regs -> smem (hi/lo)
#pragma unroll
        for (int t = 0; t < 4; t++) {
            int i = tid + t * 256;
            int r = i >> 3, c4 = (i & 7) << 2;
            uint2 hw, lw;
            split4(regA[t], hw, lw);
            *(uint2*)(Ah + r * GSTR + c4) = hw;
            *(uint2*)(Al + r * GSTR + c4) = lw;
            split4(regB[t], hw, lw);
            *(uint2*)(Bh + r * GSTR + c4) = hw;
            *(uint2*)(Bl + r * GSTR + c4) = lw;
        }
        __syncthreads();

        if (c + 1 < NCH) {
            int kt = (c + 1) * GBK;
#pragma unroll
            for (int t = 0; t < 4; t++) {
                int i = tid + t * 256;
                int r = i >> 3, c4 = (i & 7) << 2;
                regA[t] = *(const float4*)(A + (rowA0 + r) * EMB + kt + c4);
                regB[t] = *(const float4*)(B + (rowB0 + r) * EMB + kt + c4);
            }
        }

#pragma unroll
        for (int kk = 0; kk < GBK; kk += 16) {
            const uint32_t lrow = lane & 15;
            const uint32_t lcol = (lane >> 4) << 3;
            uint32_t af[4][4];
            // A hi frags
#pragma unroll
            for (int mt = 0; mt < 4; mt++) {
                uint32_t addr = sb + G_AH +
                    (uint32_t)(((wm + mt * 16 + lrow) * GSTR + kk + lcol) * 2);
                ldsm_x4(af[mt], addr);
            }
            // B hi/lo frags (x4 covers 2 n-tiles)
            uint32_t b0h[4], b1h[4], b0l[4], b1l[4];
#pragma unroll
            for (int g = 0; g < 2; g++) {
                uint32_t roff = (uint32_t)(((wn + g * 16 + lrow) * GSTR + kk + lcol) * 2);
                uint32_t r4[4];
                ldsm_x4(r4, sb + G_BH + roff);
                b0h[2 * g] = r4[0]; b0h[2 * g + 1] = r4[1];
                b1h[2 * g] = r4[2]; b1h[2 * g + 1] = r4[3];
                ldsm_x4(r4, sb + G_BL + roff);
                b0l[2 * g] = r4[0]; b0l[2 * g + 1] = r4[1];
                b1l[2 * g] = r4[2]; b1l[2 * g + 1] = r4[3];
            }
            // ah*bh + ah*bl
#pragma unroll
            for (int mt = 0; mt < 4; mt++)
#pragma unroll
                for (int nt = 0; nt < 4; nt++) {
                    mma16816(acc[mt][nt], af[mt], b0h[nt], b1h[nt]);
                    mma16816(acc[mt][nt], af[mt], b0l[nt], b1l[nt]);
                }
            // al*bh
#pragma unroll
            for (int mt = 0; mt < 4; mt++) {
                uint32_t addr = sb + G_AL +
                    (uint32_t)(((wm + mt * 16 + lrow) * GSTR + kk + lcol) * 2);
                ldsm_x4(af[mt], addr);
            }
#pragma unroll
            for (int mt = 0; mt < 4; mt++)
#pragma unroll
                for (int nt = 0; nt < 4; nt++)
                    mma16816(acc[mt][nt], af[mt], b0h[nt], b1h[nt]);
        }
        __syncthreads();
    }

    // epilogue
#pragma unroll
    for (int mt = 0; mt < 4; mt++) {
        size_t r0 = rowA0 + wm + mt * 16 + (lane >> 2);
        size_t r1 = r0 + 8;
#pragma unroll
        for (int nt = 0; nt < 4; nt++) {
            size_t cc = rowB0 + wn + nt * 8 + (lane & 3) * 2;
            *(float2*)(C + r0 * EMB + cc) = make_float2(acc[mt][nt][0], acc[mt][nt][1]);
            *(float2*)(C + r1 * EMB + cc) = make_float2(acc[mt][nt][2], acc[mt][nt][3]);
        }
    }
}

// ===========================================================================
// Flash attention with HMMA (bf16 hi/lo x3 chains), fp32 softmax.
// CTA = (qtile 64, head, batch). 8 warps: wm=wid&3 (16 q rows), wn=wid>>2
// (32 cols). K-tile 64. V via ldmatrix.trans.
// ===========================================================================
struct AttnSmem {
    __nv_bfloat16 Qh[64][72], Ql[64][72];
    __nv_bfloat16 Kh[64][72], Kl[64][72];
    __nv_bfloat16 Vh[64][72], Vl[64][72];
    __nv_bfloat16 Ph[64][72], Pl[64][72];
    float Sf[64][65];
    float m[64], l[64], alpha[64];
    unsigned char msk[64];
};

__global__ __launch_bounds__(256) void attn_mma(const float* __restrict__ Qg,
                                                const float* __restrict__ Kg,
                                                const float* __restrict__ Vg,
                                                const unsigned char* __restrict__ mask,
                                                float* __restrict__ Og)
{
    AttnSmem& s = *reinterpret_cast<AttnSmem*>(sm_raw);
    const int b  = blockIdx.z;
    const int h  = blockIdx.y;
    const int qt = blockIdx.x;
    const int tid = threadIdx.x;
    const int wid = tid >> 5;
    const int lane = tid & 31;
    const int wm = (wid & 3) * 16;   // q rows
    const int wn = (wid >> 2) * 32;  // k cols (S) / d cols (O)
    const size_t headoff = (size_t)h * HDIM;

    uint32_t sqh = smem_u32(&s.Qh[0][0]);
    uint32_t sql = smem_u32(&s.Ql[0][0]);
    uint32_t skh = smem_u32(&s.Kh[0][0]);
    uint32_t skl = smem_u32(&s.Kl[0][0]);
    uint32_t svh = smem_u32(&s.Vh[0][0]);
    uint32_t svl = smem_u32(&s.Vl[0][0]);
    uint32_t sph = smem_u32(&s.Ph[0][0]);
    uint32_t spl = smem_u32(&s.Pl[0][0]);

    if (tid < 64) { s.m[tid] = -INFINITY; s.l[tid] = 0.f; }

    // Load Q tile (64 x 64) -> hi/lo bf16
#pragma unroll
    for (int t = 0; t < 4; t++) {
        int i = tid + t * 256;
        int r = i >> 4, c4 = (i & 15) << 2;
        float4 v = *(const float4*)(Qg + ((size_t)(qt * 64 + r) * BATCH + b) * EMB
                                    + headoff + c4);
        uint2 hw, lw;
        split4(v, hw, lw);
        *(uint2*)(&s.Qh[r][c4]) = hw;
        *(uint2*)(&s.Ql[r][c4]) = lw;
    }

    float o[4][4];
#pragma unroll
    for (int nt = 0; nt < 4; nt++)
#pragma unroll
        for (int e = 0; e < 4; e++) o[nt][e] = 0.f;

    const uint32_t lrow = lane & 15;
    const uint32_t lcol = (lane >> 4) << 3;
    const int r0 = wm + (lane >> 2);
    const int r1 = r0 + 8;

    for (int kt = 0; kt < T_K / 64; kt++) {
        __syncthreads();
        // Load K, V tiles (rows = key pos) -> hi/lo
#pragma unroll
        for (int t = 0; t < 4; t++) {
            int i = tid + t * 256;
            int r = i >> 4, c4 = (i & 15) << 2;
            size_t base = ((size_t)(kt * 64 + r) * BATCH + b) * EMB + headoff + c4;
            uint2 hw, lw;
            float4 vk = *(const float4*)(Kg + base);
            split4(vk, hw, lw);
            *(uint2*)(&s.Kh[r][c4]) = hw;
            *(uint2*)(&s.Kl[r][c4]) = lw;
            float4 vv = *(const float4*)(Vg + base);
            split4(vv, hw, lw);
            *(uint2*)(&s.Vh[r][c4]) = hw;
            *(uint2*)(&s.Vl[r][c4]) = lw;
        }
        if (tid < 64) s.msk[tid] = mask[(size_t)b * T_K + kt * 64 + tid];
        __syncthreads();

        // ---- S = Q K^T : warp computes 16q x 32k ----
        float sc[4][4];
#pragma unroll
        for (int nt = 0; nt < 4; nt++)
#pragma unroll
            for (int e = 0; e < 4; e++) sc[nt][e] = 0.f;

#pragma unroll
        for (int kk = 0; kk < HDIM; kk += 16) {
            uint32_t aoff = (uint32_t)(((wm + lrow) * 72 + kk + lcol) * 2);
            uint32_t ah[4], al[4];
            ldsm_x4(ah, sqh + aoff);
            ldsm_x4(al, sql + aoff);
            uint32_t b0h[4], b1h[4], b0l[4], b1l[4];
#pragma unroll
            for (int g = 0; g < 2; g++) {
                uint32_t roff = (uint32_t)(((wn + g * 16 + lrow) * 72 + kk + lcol) * 2);
                uint32_t r4[4];
                ldsm_x4(r4, skh + roff);
                b0h[2*g] = r4[0]; b0h[2*g+1] = r4[1];
                b1h[2*g] = r4[2]; b1h[2*g+1] = r4[3];
                ldsm_x4(r4, skl + roff);
                b0l[2*g] = r4[0]; b0l[2*g+1] = r4[1];
                b1l[2*g] = r4[2]; b1l[2*g+1] = r4[3];
            }
#pragma unroll
            for (int nt = 0; nt < 4; nt++) {
                mma16816(sc[nt], ah, b0h[nt], b1h[nt]);
                mma16816(sc[nt], ah, b0l[nt], b1l[nt]);
                mma16816(sc[nt], al, b0h[nt], b1h[nt]);
            }
        }
        // scale + mask, write fp32 scores Sf[q][k]
#pragma unroll
        for (int nt = 0; nt < 4; nt++) {
            int k0 = wn + nt * 8 + (lane & 3) * 2;
            bool m0 = s.msk[k0] != 0, m1 = s.msk[k0 + 1] != 0;
            s.Sf[r0][k0]     = m0 ? NEGINF : sc[nt][0] * 0.125f;
            s.Sf[r0][k0 + 1] = m1 ? NEGINF : sc[nt][1] * 0.125f;
            s.Sf[r1][k0]     = m0 ? NEGINF : sc[nt][2] * 0.125f;
            s.Sf[r1][k0 + 1] = m1 ? NEGINF : sc[nt][3] * 0.125f;
        }
        __syncthreads();

        // ---- online softmax: warp w owns rows w*8..w*8+7 ----
        for (int rr = 0; rr < 8; rr++) {
            int q = wid * 8 + rr;
            float s0 = s.Sf[q][lane];
            float s1 = s.Sf[q][lane + 32];
            float tmax = fmaxf(s0, s1);
#pragma unroll
            for (int off = 16; off > 0; off >>= 1)
                tmax = fmaxf(tmax, __shfl_xor_sync(0xffffffffu, tmax, off));
            float mold = s.m[q];
            float mnew = fmaxf(mold, tmax);
            float p0 = __expf(s0 - mnew);
            float p1 = __expf(s1 - mnew);
            __nv_bfloat16 hh, ll;
            split1(p0, hh, ll);
            s.Ph[q][lane] = hh; s.Pl[q][lane] = ll;
            split1(p1, hh, ll);
            s.Ph[q][lane + 32] = hh; s.Pl[q][lane + 32] = ll;
            float ps = p0 + p1;
#pragma unroll
            for (int off = 16; off > 0; off >>= 1)
                ps += __shfl_xor_sync(0xffffffffu, ps, off);
            if (lane == 0) {
                float al2 = __expf(mold - mnew);
                s.alpha[q] = al2;
                s.l[q] = s.l[q] * al2 + ps;
                s.m[q] = mnew;
            }
        }
        __syncthreads();

        // ---- O = O*alpha + P V : warp computes 16q x 32d ----
        float a0 = s.alpha[r0];
        float a1 = s.alpha[r1];
#pragma unroll
        for (int nt = 0; nt < 4; nt++) {
            o[nt][0] *= a0; o[nt][1] *= a0;
            o[nt][2] *= a1; o[nt][3] *= a1;
        }
#pragma unroll
        for (int kk = 0; kk < 64; kk += 16) {
            uint32_t aoff = (uint32_t)(((wm + lrow) * 72 + kk + lcol) * 2);
            uint32_t ah[4], al[4];
            ldsm_x4(ah, sph + aoff);
            ldsm_x4(al, spl + aoff);
            // V fragments via ldmatrix.trans; x4 covers 2 d-tiles x k16
            uint32_t b0h[4], b1h[4], b0l[4], b1l[4];
#pragma unroll
            for (int g = 0; g < 2; g++) {
                uint32_t vrow = kk + (lane & 7) + ((lane >> 3) & 1) * 8;
                uint32_t vcol = wn + g * 16 + ((lane >> 4) << 3);
                uint32_t roff = (uint32_t)((vrow * 72 + vcol) * 2);
                uint32_t r4[4];
                ldsm_x4_t(r4, svh + roff);
                b0h[2*g] = r4[0]; b1h[2*g] = r4[1];
                b0h[2*g+1] = r4[2]; b1h[2*g+1] = r4[3];
                ldsm_x4_t(r4, svl + roff);
                b0l[2*g] = r4[0]; b1l[2*g] = r4[1];
                b0l[2*g+1] = r4[2]; b1l[2*g+1] = r4[3];
            }
#pragma unroll
            for (int nt = 0; nt < 4; nt++) {
                mma16816(o[nt], ah, b0h[nt], b1h[nt]);
                mma16816(o[nt], ah, b0l[nt], b1l[nt]);
                mma16816(o[nt], al, b0h[nt], b1h[nt]);
            }
        }
    }

    // finalize: divide by l, store (t, b, e)
    float inv0 = 1.f / s.l[r0];
    float inv1 = 1.f / s.l[r1];
    size_t tg0 = (size_t)(qt * 64 + r0) * BATCH + b;
    size_t tg1 = (size_t)(qt * 64 + r1) * BATCH + b;
#pragma unroll
    for (int nt = 0; nt < 4; nt++) {
        size_t d0 = wn + nt * 8 + (lane & 3) * 2;
        *(float2*)(Og + tg0 * EMB + headoff + d0) =
            make_float2(o[nt][0] * inv0, o[nt][1] * inv0);
        *(float2*)(Og + tg1 * EMB + headoff + d0) =
            make_float2(o[nt][2] * inv1, o[nt][3] * inv1);
    }
}

// ===========================================================================
// Launch
// ===========================================================================
extern "C" void kernel_launch(void* const* d_in, const int* in_sizes, int n_in,
                              void* d_out, int out_size)
{
    const float* q  = (const float*)d_in[0];
    const float* k  = (const float*)d_in[1];
    const float* v  = (const float*)d_in[2];
    const void*  maskraw = d_in[3];
    const float* Wq = (const float*)d_in[4];
    const float* Wk = (const float*)d_in[5];
    const float* Wv = (const float*)d_in[6];
    const float* Wo = (const float*)d_in[7];
    float* out = (float*)d_out;

    float *gq, *gk, *gv, *gao;
    unsigned char* gmask;
    cudaGetSymbolAddress((void**)&gq,  g_Q);
    cudaGetSymbolAddress((void**)&gk,  g_K);
    cudaGetSymbolAddress((void**)&gv,  g_V);
    cudaGetSymbolAddress((void**)&gao, g_AO);
    cudaGetSymbolAddress((void**)&gmask, g_mask);

    const int attn_smem = (int)sizeof(AttnSmem);
    cudaFuncSetAttribute(attn_mma, cudaFuncAttributeMaxDynamicSharedMemorySize,
                         attn_smem);
    cudaFuncSetAttribute(gemm_mma, cudaFuncAttributeMaxDynamicSharedMemorySize,
                         GEMM_SMEM);

    sniff_mask_kernel<<<1, 256>>>((const unsigned char*)maskraw);
    norm_mask_kernel<<<NMASK / 256, 256>>>(maskraw);

    dim3 ggrid(EMB / GBN, MROWS / GBM);   // (8, 64)
    gemm_mma<<<ggrid, 256, GEMM_SMEM>>>(q, Wq, gq);
    gemm_mma<<<ggrid, 256, GEMM_SMEM>>>(k, Wk, gk);
    gemm_mma<<<ggrid, 256, GEMM_SMEM>>>(v, Wv, gv);

    dim3 agrid(T_Q / 64, NHEADS, BATCH);  // (32, 16, 4)
    attn_mma<<<agrid, 256, attn_smem>>>(gq, gk, gv, gmask, gao);

    gemm_mma<<<ggrid, 256, GEMM_SMEM>>>(gao, Wo, out);
}

// round 6
// speedup vs baseline: 2.0426x; 1.0728x over previous
#include <cuda_runtime.h>
#include <cuda_bf16.h>
#include <math.h>
#include <stdint.h>

#define T_Q 2048
#define T_K 2048
#define BATCH 4
#define EMB 1024
#define NHEADS 16
#define HDIM 64
#define MROWS (T_Q * BATCH)   // 8192
#define NEGINF -1e9f
#define NMASK (BATCH * T_K)   // 8192

// ---------------------------------------------------------------------------
// Static device scratch (no allocation allowed). All bf16 hi/lo pairs.
// ---------------------------------------------------------------------------
__device__ __nv_bfloat16 c_qh[MROWS * EMB], c_ql[MROWS * EMB];
__device__ __nv_bfloat16 c_kh[MROWS * EMB], c_kl[MROWS * EMB];
__device__ __nv_bfloat16 c_vh[MROWS * EMB], c_vl[MROWS * EMB];
__device__ __nv_bfloat16 c_wqh[EMB * EMB], c_wql[EMB * EMB];
__device__ __nv_bfloat16 c_wkh[EMB * EMB], c_wkl[EMB * EMB];
__device__ __nv_bfloat16 c_wvh[EMB * EMB], c_wvl[EMB * EMB];
__device__ __nv_bfloat16 c_woh[EMB * EMB], c_wol[EMB * EMB];
__device__ __nv_bfloat16 p_qh[MROWS * EMB], p_ql[MROWS * EMB];
__device__ __nv_bfloat16 p_kh[MROWS * EMB], p_kl[MROWS * EMB];
__device__ __nv_bfloat16 p_vh[MROWS * EMB], p_vl[MROWS * EMB];
__device__ __nv_bfloat16 ao_h[MROWS * EMB], ao_l[MROWS * EMB];
__device__ unsigned char g_mask[NMASK];
__device__ int g_mask_kind;

// ===========================================================================
// helpers
// ===========================================================================
__device__ __forceinline__ uint32_t smem_u32(const void* p) {
    uint32_t a;
    asm("{ .reg .u64 t; cvta.to.shared.u64 t, %1; cvt.u32.u64 %0, t; }"
        : "=r"(a) : "l"(p));
    return a;
}
__device__ __forceinline__ void mma16816(float* c, const uint32_t* a,
                                         uint32_t b0, uint32_t b1) {
    asm volatile(
        "mma.sync.aligned.m16n8k16.row.col.f32.bf16.bf16.f32 "
        "{%0,%1,%2,%3}, {%4,%5,%6,%7}, {%8,%9}, {%0,%1,%2,%3};"
        : "+f"(c[0]), "+f"(c[1]), "+f"(c[2]), "+f"(c[3])
        : "r"(a[0]), "r"(a[1]), "r"(a[2]), "r"(a[3]), "r"(b0), "r"(b1));
}
__device__ __forceinline__ void ldsm_x4(uint32_t* r, uint32_t addr) {
    asm volatile("ldmatrix.sync.aligned.m8n8.x4.shared.b16 {%0,%1,%2,%3}, [%4];"
        : "=r"(r[0]), "=r"(r[1]), "=r"(r[2]), "=r"(r[3]) : "r"(addr));
}
__device__ __forceinline__ void ldsm_x4_t(uint32_t* r, uint32_t addr) {
    asm volatile("ldmatrix.sync.aligned.m8n8.x4.trans.shared.b16 {%0,%1,%2,%3}, [%4];"
        : "=r"(r[0]), "=r"(r[1]), "=r"(r[2]), "=r"(r[3]) : "r"(addr));
}
__device__ __forceinline__ void cp16(uint32_t sm, const void* g) {
    asm volatile("cp.async.cg.shared.global [%0], [%1], 16;" :: "r"(sm), "l"(g));
}
#define CP_COMMIT() asm volatile("cp.async.commit_group;" ::: "memory")
#define CP_WAIT(n)  asm volatile("cp.async.wait_group %0;" :: "n"(n) : "memory")

__device__ __forceinline__ void split1(float x, __nv_bfloat16& h, __nv_bfloat16& l) {
    h = __float2bfloat16(x);
    l = __float2bfloat16(x - __bfloat162float(h));
}
__device__ __forceinline__ uint32_t pack2(__nv_bfloat16 a, __nv_bfloat16 b) {
    return (uint32_t)__bfloat16_as_ushort(a) | ((uint32_t)__bfloat16_as_ushort(b) << 16);
}
__device__ __forceinline__ void split4(float4 v, uint2& hw, uint2& lw) {
    __nv_bfloat16 h0, h1, h2, h3, l0, l1, l2, l3;
    split1(v.x, h0, l0); split1(v.y, h1, l1);
    split1(v.z, h2, l2); split1(v.w, h3, l3);
    hw.x = pack2(h0, h1); hw.y = pack2(h2, h3);
    lw.x = pack2(l0, l1); lw.y = pack2(l2, l3);
}

// ===========================================================================
// fp32 -> bf16 hi/lo converter (elementwise)
// ===========================================================================
__global__ void conv_split(const float* __restrict__ x,
                           __nv_bfloat16* __restrict__ h,
                           __nv_bfloat16* __restrict__ l, int n)
{
    int i = (blockIdx.x * blockDim.x + threadIdx.x) * 4;
    if (i >= n) return;
    float4 v = *(const float4*)(x + i);
    uint2 hw, lw;
    split4(v, hw, lw);
    *(uint2*)(h + i) = hw;
    *(uint2*)(l + i) = lw;
}

// ===========================================================================
// Mask dtype sniff + normalization (verified R3)
// ===========================================================================
__global__ void sniff_mask_kernel(const unsigned char* __restrict__ m)
{
    __shared__ int nz_off, nz_al;
    if (threadIdx.x == 0) { nz_off = 0; nz_al = 0; }
    __syncthreads();
    int loc_off = 0, loc_al = 0;
    for (int i = threadIdx.x; i < NMASK; i += blockDim.x) {
        unsigned char v = m[i];
        if (v) { if (i & 3) loc_off = 1; else loc_al = 1; }
    }
    if (loc_off) atomicOr(&nz_off, 1);
    if (loc_al)  atomicOr(&nz_al, 1);
    __syncthreads();
    if (threadIdx.x == 0) {
        int kind;
        if (!nz_off)     kind = 1;
        else if (!nz_al) kind = 2;
        else             kind = 0;
        g_mask_kind = kind;
    }
}

__global__ void norm_mask_kernel(const void* __restrict__ m)
{
    int i = blockIdx.x * blockDim.x + threadIdx.x;
    if (i >= NMASK) return;
    int kind = g_mask_kind;
    unsigned char r;
    if (kind == 1)      r = (((const int*)m)[i]   != 0);
    else if (kind == 2) r = (((const float*)m)[i] != 0.f);
    else                r = (((const unsigned char*)m)[i] != 0);
    g_mask[i] = r;
}

// ===========================================================================
// HMMA GEMM NT on preconverted bf16 hi/lo: C = A * B^T (3 chains).
// CTA 128x128, BK=32, cp.async 2-stage pipeline, warp tile 64x32.
// OUTMODE 0: fp32 C. OUTMODE 1: bf16 hi/lo C.
// ===========================================================================
#define GBM 128
#define GBN 128
#define GBK 32
#define GSTR 40                       // bf16 elements per smem row (80B)
#define ARR_SZ (128 * GSTR * 2)       // 10240 B per array
#define STAGE_SZ (4 * ARR_SZ)         // AH, AL, BH, BL
#define GEMM_SMEM (2 * STAGE_SZ)      // 81920 B
#define O_AH 0
#define O_AL ARR_SZ
#define O_BH (2 * ARR_SZ)
#define O_BL (3 * ARR_SZ)

extern __shared__ char sm_raw[];

template <int OUTMODE>
__global__ __launch_bounds__(256, 2) void gemm_bf16(
    const __nv_bfloat16* __restrict__ Agh, const __nv_bfloat16* __restrict__ Agl,
    const __nv_bfloat16* __restrict__ Bgh, const __nv_bfloat16* __restrict__ Bgl,
    float* __restrict__ Cf,
    __nv_bfloat16* __restrict__ Ch, __nv_bfloat16* __restrict__ Cl)
{
    uint32_t sb = smem_u32(sm_raw);
    const int tid = threadIdx.x;
    const int wid = tid >> 5;
    const int lane = tid & 31;
    const int wm = (wid & 1) * 64;
    const int wn = (wid >> 1) * 32;
    const size_t rowA0 = (size_t)blockIdx.y * GBM;
    const size_t rowB0 = (size_t)blockIdx.x * GBN;

    // per-thread cp.async assignment: 8 x 16B copies
    const int carr = tid >> 6;            // 0..3 -> AH, AL, BH, BL
    const int crow0 = (tid & 63) >> 1;    // 0..31 base row (x4 rows step 32)
    const int cseg = (tid & 1) << 1;      // 0 or 2 (two 16B segs each)
    const __nv_bfloat16* gbase[4] = {
        Agh + rowA0 * EMB, Agl + rowA0 * EMB,
        Bgh + rowB0 * EMB, Bgl + rowB0 * EMB };
    const __nv_bfloat16* mygb = gbase[carr];
    const uint32_t myarr = sb + carr * ARR_SZ;

    float acc[4][4][4];
#pragma unroll
    for (int mt = 0; mt < 4; mt++)
#pragma unroll
        for (int nt = 0; nt < 4; nt++)
#pragma unroll
            for (int e = 0; e < 4; e++) acc[mt][nt][e] = 0.f;

    const int NCH = EMB / GBK;   // 32

    // prologue: prefetch chunk 0 -> stage 0
#pragma unroll
    for (int rr = 0; rr < 4; rr++) {
        int row = crow0 + rr * 32;
        uint32_t smaddr = myarr + row * (GSTR * 2) + cseg * 16;
        const void* g = mygb + (size_t)row * EMB + cseg * 8;
        cp16(smaddr, g);
        cp16(smaddr + 16, (const char*)g + 16);
    }
    CP_COMMIT();

    for (int c = 0; c < NCH; c++) {
        const uint32_t stage = (uint32_t)(c & 1);
        if (c + 1 < NCH) {
            const int kt = (c + 1) * GBK;
            const uint32_t stb = myarr + ((c + 1) & 1) * STAGE_SZ;
#pragma unroll
            for (int rr = 0; rr < 4; rr++) {
                int row = crow0 + rr * 32;
                uint32_t smaddr = stb + row * (GSTR * 2) + cseg * 16;
                const void* g = mygb + (size_t)row * EMB + kt + cseg * 8;
                cp16(smaddr, g);
                cp16(smaddr + 16, (const char*)g + 16);
            }
            CP_COMMIT();
            CP_WAIT(1);
        } else {
            CP_WAIT(0);
        }
        __syncthreads();

        const uint32_t base = sb + stage * STAGE_SZ;
        const uint32_t lrow = lane & 15;
        const uint32_t lcol = (lane >> 4) << 3;
#pragma unroll
        for (int kk = 0; kk < GBK; kk += 16) {
            uint32_t af[4][4];
#pragma unroll
            for (int mt = 0; mt < 4; mt++) {
                uint32_t addr = base + O_AH +
                    (uint32_t)(((wm + mt * 16 + lrow) * GSTR + kk + lcol) * 2);
                ldsm_x4(af[mt], addr);
            }
            uint32_t b0h[4], b1h[4], b0l[4], b1l[4];
#pragma unroll
            for (int g = 0; g < 2; g++) {
                uint32_t roff = (uint32_t)(((wn + g * 16 + lrow) * GSTR + kk + lcol) * 2);
                uint32_t r4[4];
                ldsm_x4(r4, base + O_BH + roff);
                b0h[2 * g] = r4[0]; b0h[2 * g + 1] = r4[1];
                b1h[2 * g] = r4[2]; b1h[2 * g + 1] = r4[3];
                ldsm_x4(r4, base + O_BL + roff);
                b0l[2 * g] = r4[0]; b0l[2 * g + 1] = r4[1];
                b1l[2 * g] = r4[2]; b1l[2 * g + 1] = r4[3];
            }
#pragma unroll
            for (int mt = 0; mt < 4; mt++)
#pragma unroll
                for (int nt = 0; nt < 4; nt++) {
                    mma16816(acc[mt][nt], af[mt], b0h[nt], b1h[nt]);
                    mma16816(acc[mt][nt], af[mt], b0l[nt], b1l[nt]);
                }
#pragma unroll
            for (int mt = 0; mt < 4; mt++) {
                uint32_t addr = base + O_AL +
                    (uint32_t)(((wm + mt * 16 + lrow) * GSTR + kk + lcol) * 2);
                ldsm_x4(af[mt], addr);
            }
#pragma unroll
            for (int mt = 0; mt < 4; mt++)
#pragma unroll
                for (int nt = 0; nt < 4; nt++)
                    mma16816(acc[mt][nt], af[mt], b0h[nt], b1h[nt]);
        }
        __syncthreads();
    }

    // epilogue
#pragma unroll
    for (int mt = 0; mt < 4; mt++) {
        size_t r0 = rowA0 + wm + mt * 16 + (lane >> 2);
        size_t r1 = r0 + 8;
#pragma unroll
        for (int nt = 0; nt < 4; nt++) {
            size_t cc = rowB0 + wn + nt * 8 + (lane & 3) * 2;
            if (OUTMODE == 0) {
                *(float2*)(Cf + r0 * EMB + cc) = make_float2(acc[mt][nt][0], acc[mt][nt][1]);
                *(float2*)(Cf + r1 * EMB + cc) = make_float2(acc[mt][nt][2], acc[mt][nt][3]);
            } else {
                __nv_bfloat16 h0, l0, h1, l1;
                split1(acc[mt][nt][0], h0, l0);
                split1(acc[mt][nt][1], h1, l1);
                *(uint32_t*)(Ch + r0 * EMB + cc) = pack2(h0, h1);
                *(uint32_t*)(Cl + r0 * EMB + cc) = pack2(l0, l1);
                split1(acc[mt][nt][2], h0, l0);
                split1(acc[mt][nt][3], h1, l1);
                *(uint32_t*)(Ch + r1 * EMB + cc) = pack2(h0, h1);
                *(uint32_t*)(Cl + r1 * EMB + cc) = pack2(l0, l1);
            }
        }
    }
}

// ===========================================================================
// Flash attention with HMMA on preconverted bf16 hi/lo Q/K/V.
// CTA = (64 q, head, batch). Writes AO as bf16 hi/lo.
// ===========================================================================
struct AttnSmem {
    __nv_bfloat16 Qh[64][72], Ql[64][72];
    __nv_bfloat16 Kh[64][72], Kl[64][72];
    __nv_bfloat16 Vh[64][72], Vl[64][72];
    __nv_bfloat16 Ph[64][72], Pl[64][72];
    float Sf[64][65];
    float m[64], l[64], alpha[64];
    unsigned char msk[64];
};

__global__ __launch_bounds__(256) void attn_mma(
    const __nv_bfloat16* __restrict__ Qhg, const __nv_bfloat16* __restrict__ Qlg,
    const __nv_bfloat16* __restrict__ Khg, const __nv_bfloat16* __restrict__ Klg,
    const __nv_bfloat16* __restrict__ Vhg, const __nv_bfloat16* __restrict__ Vlg,
    const unsigned char* __restrict__ mask,
    __nv_bfloat16* __restrict__ Ohg, __nv_bfloat16* __restrict__ Olg)
{
    AttnSmem& s = *reinterpret_cast<AttnSmem*>(sm_raw);
    const int b  = blockIdx.z;
    const int h  = blockIdx.y;
    const int qt = blockIdx.x;
    const int tid = threadIdx.x;
    const int wid = tid >> 5;
    const int lane = tid & 31;
    const int wm = (wid & 3) * 16;
    const int wn = (wid >> 2) * 32;
    const size_t headoff = (size_t)h * HDIM;

    uint32_t sqh = smem_u32(&s.Qh[0][0]);
    uint32_t sql = smem_u32(&s.Ql[0][0]);
    uint32_t skh = smem_u32(&s.Kh[0][0]);
    uint32_t skl = smem_u32(&s.Kl[0][0]);
    uint32_t svh = smem_u32(&s.Vh[0][0]);
    uint32_t svl = smem_u32(&s.Vl[0][0]);
    uint32_t sph = smem_u32(&s.Ph[0][0]);
    uint32_t spl = smem_u32(&s.Pl[0][0]);

    if (tid < 64) { s.m[tid] = -INFINITY; s.l[tid] = 0.f; }

    // Load Q tile (64x64 bf16 hi/lo)
#pragma unroll
    for (int t = 0; t < 4; t++) {
        int i = tid + t * 256;
        int r = i >> 4, c4 = (i & 15) << 2;
        size_t gi = ((size_t)(qt * 64 + r) * BATCH + b) * EMB + headoff + c4;
        *(uint2*)(&s.Qh[r][c4]) = *(const uint2*)(Qhg + gi);
        *(uint2*)(&s.Ql[r][c4]) = *(const uint2*)(Qlg + gi);
    }

    float o[4][4];
#pragma unroll
    for (int nt = 0; nt < 4; nt++)
#pragma unroll
        for (int e = 0; e < 4; e++) o[nt][e] = 0.f;

    const uint32_t lrow = lane & 15;
    const uint32_t lcol = (lane >> 4) << 3;
    const int r0 = wm + (lane >> 2);
    const int r1 = r0 + 8;

    for (int kt = 0; kt < T_K / 64; kt++) {
        __syncthreads();
#pragma unroll
        for (int t = 0; t < 4; t++) {
            int i = tid + t * 256;
            int r = i >> 4, c4 = (i & 15) << 2;
            size_t gi = ((size_t)(kt * 64 + r) * BATCH + b) * EMB + headoff + c4;
            *(uint2*)(&s.Kh[r][c4]) = *(const uint2*)(Khg + gi);
            *(uint2*)(&s.Kl[r][c4]) = *(const uint2*)(Klg + gi);
            *(uint2*)(&s.Vh[r][c4]) = *(const uint2*)(Vhg + gi);
            *(uint2*)(&s.Vl[r][c4]) = *(const uint2*)(Vlg + gi);
        }
        if (tid < 64) s.msk[tid] = mask[(size_t)b * T_K + kt * 64 + tid];
        __syncthreads();

        // ---- S = Q K^T ----
        float sc[4][4];
#pragma unroll
        for (int nt = 0; nt < 4; nt++)
#pragma unroll
            for (int e = 0; e < 4; e++) sc[nt][e] = 0.f;

#pragma unroll
        for (int kk = 0; kk < HDIM; kk += 16) {
            uint32_t aoff = (uint32_t)(((wm + lrow) * 72 + kk + lcol) * 2);
            uint32_t ah[4], al[4];
            ldsm_x4(ah, sqh + aoff);
            ldsm_x4(al, sql + aoff);
            uint32_t b0h[4], b1h[4], b0l[4], b1l[4];
#pragma unroll
            for (int g = 0; g < 2; g++) {
                uint32_t roff = (uint32_t)(((wn + g * 16 + lrow) * 72 + kk + lcol) * 2);
                uint32_t r4[4];
                ldsm_x4(r4, skh + roff);
                b0h[2*g] = r4[0]; b0h[2*g+1] = r4[1];
                b1h[2*g] = r4[2]; b1h[2*g+1] = r4[3];
                ldsm_x4(r4, skl + roff);
                b0l[2*g] = r4[0]; b0l[2*g+1] = r4[1];
                b1l[2*g] = r4[2]; b1l[2*g+1] = r4[3];
            }
#pragma unroll
            for (int nt = 0; nt < 4; nt++) {
                mma16816(sc[nt], ah, b0h[nt], b1h[nt]);
                mma16816(sc[nt], ah, b0l[nt], b1l[nt]);
                mma16816(sc[nt], al, b0h[nt], b1h[nt]);
            }
        }
#pragma unroll
        for (int nt = 0; nt < 4; nt++) {
            int k0 = wn + nt * 8 + (lane & 3) * 2;
            bool m0 = s.msk[k0] != 0, m1 = s.msk[k0 + 1] != 0;
            s.Sf[r0][k0]     = m0 ? NEGINF : sc[nt][0] * 0.125f;
            s.Sf[r0][k0 + 1] = m1 ? NEGINF : sc[nt][1] * 0.125f;
            s.Sf[r1][k0]     = m0 ? NEGINF : sc[nt][2] * 0.125f;
            s.Sf[r1][k0 + 1] = m1 ? NEGINF : sc[nt][3] * 0.125f;
        }
        __syncthreads();

        // ---- online softmax (warp w: rows w*8..w*8+7) ----
        for (int rr = 0; rr < 8; rr++) {
            int q = wid * 8 + rr;
            float s0 = s.Sf[q][lane];
            float s1 = s.Sf[q][lane + 32];
            float tmax = fmaxf(s0, s1);
#pragma unroll
            for (int off = 16; off > 0; off >>= 1)
                tmax = fmaxf(tmax, __shfl_xor_sync(0xffffffffu, tmax, off));
            float mold = s.m[q];
            float mnew = fmaxf(mold, tmax);
            float p0 = __expf(s0 - mnew);
            float p1 = __expf(s1 - mnew);
            __nv_bfloat16 hh, ll;
            split1(p0, hh, ll);
            s.Ph[q][lane] = hh; s.Pl[q][lane] = ll;
            split1(p1, hh, ll);
            s.Ph[q][lane + 32] = hh; s.Pl[q][lane + 32] = ll;
            float ps = p0 + p1;
#pragma unroll
            for (int off = 16; off > 0; off >>= 1)
                ps += __shfl_xor_sync(0xffffffffu, ps, off);
            if (lane == 0) {
                float al2 = __expf(mold - mnew);
                s.alpha[q] = al2;
                s.l[q] = s.l[q] * al2 + ps;
                s.m[q] = mnew;
            }
        }
        __syncthreads();

        // ---- O = O*alpha + P V ----
        float a0 = s.alpha[r0];
        float a1 = s.alpha[r1];
#pragma unroll
        for (int nt = 0; nt < 4; nt++) {
            o[nt][0] *= a0; o[nt][1] *= a0;
            o[nt][2] *= a1; o[nt][3] *= a1;
        }
#pragma unroll
        for (int kk = 0; kk < 64; kk += 16) {
            uint32_t aoff = (uint32_t)(((wm + lrow) * 72 + kk + lcol) * 2);
            uint32_t ah[4], al[4];
            ldsm_x4(ah, sph + aoff);
            ldsm_x4(al, spl + aoff);
            uint32_t b0h[4], b1h[4], b0l[4], b1l[4];
#pragma unroll
            for (int g = 0; g < 2; g++) {
                uint32_t vrow = kk + (lane & 7) + ((lane >> 3) & 1) * 8;
                uint32_t vcol = wn + g * 16 + ((lane >> 4) << 3);
                uint32_t roff = (uint32_t)((vrow * 72 + vcol) * 2);
                uint32_t r4[4];
                ldsm_x4_t(r4, svh + roff);
                b0h[2*g] = r4[0]; b1h[2*g] = r4[1];
                b0h[2*g+1] = r4[2]; b1h[2*g+1] = r4[3];
                ldsm_x4_t(r4, svl + roff);
                b0l[2*g] = r4[0]; b1l[2*g] = r4[1];
                b0l[2*g+1] = r4[2]; b1l[2*g+1] = r4[3];
            }
#pragma unroll
            for (int nt = 0; nt < 4; nt++) {
                mma16816(o[nt], ah, b0h[nt], b1h[nt]);
                mma16816(o[nt], ah, b0l[nt], b1l[nt]);
                mma16816(o[nt], al, b0h[nt], b1h[nt]);
            }
        }
    }

    // finalize: divide by l, write bf16 hi/lo AO
    float inv0 = 1.f / s.l[r0];
    float inv1 = 1.f / s.l[r1];
    size_t tg0 = (size_t)(qt * 64 + r0) * BATCH + b;
    size_t tg1 = (size_t)(qt * 64 + r1) * BATCH + b;
#pragma unroll
    for (int nt = 0; nt < 4; nt++) {
        size_t d0 = wn + nt * 8 + (lane & 3) * 2;
        __nv_bfloat16 h0, l0, h1, l1;
        split1(o[nt][0] * inv0, h0, l0);
        split1(o[nt][1] * inv0, h1, l1);
        *(uint32_t*)(Ohg + tg0 * EMB + headoff + d0) = pack2(h0, h1);
        *(uint32_t*)(Olg + tg0 * EMB + headoff + d0) = pack2(l0, l1);
        split1(o[nt][2] * inv1, h0, l0);
        split1(o[nt][3] * inv1, h1, l1);
        *(uint32_t*)(Ohg + tg1 * EMB + headoff + d0) = pack2(h0, h1);
        *(uint32_t*)(Olg + tg1 * EMB + headoff + d0) = pack2(l0, l1);
    }
}

// ===========================================================================
// Launch
// ===========================================================================
extern "C" void kernel_launch(void* const* d_in, const int* in_sizes, int n_in,
                              void* d_out, int out_size)
{
    const float* q  = (const float*)d_in[0];
    const float* k  = (const float*)d_in[1];
    const float* v  = (const float*)d_in[2];
    const void*  maskraw = d_in[3];
    const float* Wq = (const float*)d_in[4];
    const float* Wk = (const float*)d_in[5];
    const float* Wv = (const float*)d_in[6];
    const float* Wo = (const float*)d_in[7];
    float* out = (float*)d_out;

    // symbol addresses
    __nv_bfloat16 *qh, *ql, *kh, *kl, *vh, *vl;
    __nv_bfloat16 *wqh, *wql, *wkh, *wkl, *wvh, *wvl, *woh, *wol;
    __nv_bfloat16 *pqh, *pql, *pkh, *pkl, *pvh, *pvl, *aoh, *aol;
    unsigned char* gmask;
    cudaGetSymbolAddress((void**)&qh, c_qh);  cudaGetSymbolAddress((void**)&ql, c_ql);
    cudaGetSymbolAddress((void**)&kh, c_kh);  cudaGetSymbolAddress((void**)&kl, c_kl);
    cudaGetSymbolAddress((void**)&vh, c_vh);  cudaGetSymbolAddress((void**)&vl, c_vl);
    cudaGetSymbolAddress((void**)&wqh, c_wqh); cudaGetSymbolAddress((void**)&wql, c_wql);
    cudaGetSymbolAddress((void**)&wkh, c_wkh); cudaGetSymbolAddress((void**)&wkl, c_wkl);
    cudaGetSymbolAddress((void**)&wvh, c_wvh); cudaGetSymbolAddress((void**)&wvl, c_wvl);
    cudaGetSymbolAddress((void**)&woh, c_woh); cudaGetSymbolAddress((void**)&wol, c_wol);
    cudaGetSymbolAddress((void**)&pqh, p_qh);  cudaGetSymbolAddress((void**)&pql, p_ql);
    cudaGetSymbolAddress((void**)&pkh, p_kh);  cudaGetSymbolAddress((void**)&pkl, p_kl);
    cudaGetSymbolAddress((void**)&pvh, p_vh);  cudaGetSymbolAddress((void**)&pvl, p_vl);
    cudaGetSymbolAddress((void**)&aoh, ao_h);  cudaGetSymbolAddress((void**)&aol, ao_l);
    cudaGetSymbolAddress((void**)&gmask, g_mask);

    const int attn_smem = (int)sizeof(AttnSmem);
    cudaFuncSetAttribute(attn_mma, cudaFuncAttributeMaxDynamicSharedMemorySize,
                         attn_smem);
    cudaFuncSetAttribute(gemm_bf16<0>, cudaFuncAttributeMaxDynamicSharedMemorySize,
                         GEMM_SMEM);
    cudaFuncSetAttribute(gemm_bf16<1>, cudaFuncAttributeMaxDynamicSharedMemorySize,
                         GEMM_SMEM);

    // mask
    sniff_mask_kernel<<<1, 256>>>((const unsigned char*)maskraw);
    norm_mask_kernel<<<NMASK / 256, 256>>>(maskraw);

    // fp32 -> bf16 hi/lo conversions
    const int NIN = MROWS * EMB;     // 8M
    const int NW  = EMB * EMB;       // 1M
    conv_split<<<NIN / 4 / 256, 256>>>(q,  qh,  ql,  NIN);
    conv_split<<<NIN / 4 / 256, 256>>>(k,  kh,  kl,  NIN);
    conv_split<<<NIN / 4 / 256, 256>>>(v,  vh,  vl,  NIN);
    conv_split<<<NW  / 4 / 256, 256>>>(Wq, wqh, wql, NW);
    conv_split<<<NW  / 4 / 256, 256>>>(Wk, wkh, wkl, NW);
    conv_split<<<NW  / 4 / 256, 256>>>(Wv, wvh, wvl, NW);
    conv_split<<<NW  / 4 / 256, 256>>>(Wo, woh, wol, NW);

    dim3 ggrid(EMB / GBN, MROWS / GBM);   // (8, 64)
    gemm_bf16<1><<<ggrid, 256, GEMM_SMEM>>>(qh, ql, wqh, wql, nullptr, pqh, pql);
    gemm_bf16<1><<<ggrid, 256, GEMM_SMEM>>>(kh, kl, wkh, wkl, nullptr, pkh, pkl);
    gemm_bf16<1><<<ggrid, 256, GEMM_SMEM>>>(vh, vl, wvh, wvl, nullptr, pvh, pvl);

    dim3 agrid(T_Q / 64, NHEADS, BATCH);  // (32, 16, 4)
    attn_mma<<<agrid, 256, attn_smem>>>(pqh, pql, pkh, pkl, pvh, pvl, gmask,
                                        aoh, aol);

    gemm_bf16<0><<<ggrid, 256, GEMM_SMEM>>>(aoh, aol, woh, wol, out,
                                            nullptr, nullptr);
}

// round 7
// speedup vs baseline: 2.7319x; 1.3374x over previous
#include <cuda_runtime.h>
#include <cuda_bf16.h>
#include <math.h>
#include <stdint.h>

#define T_Q 2048
#define T_K 2048
#define BATCH 4
#define EMB 1024
#define NHEADS 16
#define HDIM 64
#define MROWS (T_Q * BATCH)   // 8192
#define NEGINF -1e9f
#define NMASK (BATCH * T_K)   // 8192

// ---------------------------------------------------------------------------
// Static device scratch. All bf16 hi/lo pairs.
// ---------------------------------------------------------------------------
__device__ __nv_bfloat16 c_qh[MROWS * EMB], c_ql[MROWS * EMB];
__device__ __nv_bfloat16 c_kh[MROWS * EMB], c_kl[MROWS * EMB];
__device__ __nv_bfloat16 c_vh[MROWS * EMB], c_vl[MROWS * EMB];
__device__ __nv_bfloat16 c_wqh[EMB * EMB], c_wql[EMB * EMB];
__device__ __nv_bfloat16 c_wkh[EMB * EMB], c_wkl[EMB * EMB];
__device__ __nv_bfloat16 c_wvh[EMB * EMB], c_wvl[EMB * EMB];
__device__ __nv_bfloat16 c_woh[EMB * EMB], c_wol[EMB * EMB];
__device__ __nv_bfloat16 p_qh[MROWS * EMB], p_ql[MROWS * EMB];
__device__ __nv_bfloat16 p_kh[MROWS * EMB], p_kl[MROWS * EMB];
__device__ __nv_bfloat16 p_vh[MROWS * EMB], p_vl[MROWS * EMB];
__device__ __nv_bfloat16 ao_h[MROWS * EMB], ao_l[MROWS * EMB];
__device__ __align__(16) unsigned char g_mask[NMASK];
__device__ int g_mask_kind;

// ===========================================================================
// helpers
// ===========================================================================
__device__ __forceinline__ uint32_t smem_u32(const void* p) {
    uint32_t a;
    asm("{ .reg .u64 t; cvta.to.shared.u64 t, %1; cvt.u32.u64 %0, t; }"
        : "=r"(a) : "l"(p));
    return a;
}
__device__ __forceinline__ void mma16816(float* c, const uint32_t* a,
                                         uint32_t b0, uint32_t b1) {
    asm volatile(
        "mma.sync.aligned.m16n8k16.row.col.f32.bf16.bf16.f32 "
        "{%0,%1,%2,%3}, {%4,%5,%6,%7}, {%8,%9}, {%0,%1,%2,%3};"
        : "+f"(c[0]), "+f"(c[1]), "+f"(c[2]), "+f"(c[3])
        : "r"(a[0]), "r"(a[1]), "r"(a[2]), "r"(a[3]), "r"(b0), "r"(b1));
}
__device__ __forceinline__ void ldsm_x4(uint32_t* r, uint32_t addr) {
    asm volatile("ldmatrix.sync.aligned.m8n8.x4.shared.b16 {%0,%1,%2,%3}, [%4];"
        : "=r"(r[0]), "=r"(r[1]), "=r"(r[2]), "=r"(r[3]) : "r"(addr));
}
__device__ __forceinline__ void ldsm_x4_t(uint32_t* r, uint32_t addr) {
    asm volatile("ldmatrix.sync.aligned.m8n8.x4.trans.shared.b16 {%0,%1,%2,%3}, [%4];"
        : "=r"(r[0]), "=r"(r[1]), "=r"(r[2]), "=r"(r[3]) : "r"(addr));
}
__device__ __forceinline__ void cp16(uint32_t sm, const void* g) {
    asm volatile("cp.async.cg.shared.global [%0], [%1], 16;" :: "r"(sm), "l"(g));
}
#define CP_COMMIT() asm volatile("cp.async.commit_group;" ::: "memory")
#define CP_WAIT(n)  asm volatile("cp.async.wait_group %0;" :: "n"(n) : "memory")

__device__ __forceinline__ void split1(float x, __nv_bfloat16& h, __nv_bfloat16& l) {
    h = __float2bfloat16(x);
    l = __float2bfloat16(x - __bfloat162float(h));
}
__device__ __forceinline__ uint32_t pack2(__nv_bfloat16 a, __nv_bfloat16 b) {
    return (uint32_t)__bfloat16_as_ushort(a) | ((uint32_t)__bfloat16_as_ushort(b) << 16);
}
__device__ __forceinline__ void split4(float4 v, uint2& hw, uint2& lw) {
    __nv_bfloat16 h0, h1, h2, h3, l0, l1, l2, l3;
    split1(v.x, h0, l0); split1(v.y, h1, l1);
    split1(v.z, h2, l2); split1(v.w, h3, l3);
    hw.x = pack2(h0, h1); hw.y = pack2(h2, h3);
    lw.x = pack2(l0, l1); lw.y = pack2(l2, l3);
}

// ===========================================================================
// batched fp32 -> bf16 hi/lo converters
// ===========================================================================
__global__ void conv_qkv(const float* __restrict__ q, const float* __restrict__ k,
                         const float* __restrict__ v,
                         __nv_bfloat16* __restrict__ qh, __nv_bfloat16* __restrict__ ql,
                         __nv_bfloat16* __restrict__ kh, __nv_bfloat16* __restrict__ kl,
                         __nv_bfloat16* __restrict__ vh, __nv_bfloat16* __restrict__ vl)
{
    const float* x = (blockIdx.y == 0) ? q : (blockIdx.y == 1) ? k : v;
    __nv_bfloat16* h = (blockIdx.y == 0) ? qh : (blockIdx.y == 1) ? kh : vh;
    __nv_bfloat16* l = (blockIdx.y == 0) ? ql : (blockIdx.y == 1) ? kl : vl;
    int i = (blockIdx.x * blockDim.x + threadIdx.x) * 4;
    float4 vv = *(const float4*)(x + i);
    uint2 hw, lw;
    split4(vv, hw, lw);
    *(uint2*)(h + i) = hw;
    *(uint2*)(l + i) = lw;
}

__global__ void conv_w(const float* __restrict__ w0, const float* __restrict__ w1,
                       const float* __restrict__ w2, const float* __restrict__ w3,
                       __nv_bfloat16* __restrict__ h0, __nv_bfloat16* __restrict__ l0,
                       __nv_bfloat16* __restrict__ h1, __nv_bfloat16* __restrict__ l1,
                       __nv_bfloat16* __restrict__ h2, __nv_bfloat16* __restrict__ l2,
                       __nv_bfloat16* __restrict__ h3, __nv_bfloat16* __restrict__ l3)
{
    int wsel = blockIdx.y;
    const float* x = (wsel == 0) ? w0 : (wsel == 1) ? w1 : (wsel == 2) ? w2 : w3;
    __nv_bfloat16* h = (wsel == 0) ? h0 : (wsel == 1) ? h1 : (wsel == 2) ? h2 : h3;
    __nv_bfloat16* l = (wsel == 0) ? l0 : (wsel == 1) ? l1 : (wsel == 2) ? l2 : l3;
    int i = (blockIdx.x * blockDim.x + threadIdx.x) * 4;
    float4 vv = *(const float4*)(x + i);
    uint2 hw, lw;
    split4(vv, hw, lw);
    *(uint2*)(h + i) = hw;
    *(uint2*)(l + i) = lw;
}

// ===========================================================================
// Mask dtype sniff + normalization (verified R3)
// ===========================================================================
__global__ void sniff_mask_kernel(const unsigned char* __restrict__ m)
{
    __shared__ int nz_off, nz_al;
    if (threadIdx.x == 0) { nz_off = 0; nz_al = 0; }
    __syncthreads();
    int loc_off = 0, loc_al = 0;
    for (int i = threadIdx.x; i < NMASK; i += blockDim.x) {
        unsigned char v = m[i];
        if (v) { if (i & 3) loc_off = 1; else loc_al = 1; }
    }
    if (loc_off) atomicOr(&nz_off, 1);
    if (loc_al)  atomicOr(&nz_al, 1);
    __syncthreads();
    if (threadIdx.x == 0) {
        int kind;
        if (!nz_off)     kind = 1;
        else if (!nz_al) kind = 2;
        else             kind = 0;
        g_mask_kind = kind;
    }
}

__global__ void norm_mask_kernel(const void* __restrict__ m)
{
    int i = blockIdx.x * blockDim.x + threadIdx.x;
    if (i >= NMASK) return;
    int kind = g_mask_kind;
    unsigned char r;
    if (kind == 1)      r = (((const int*)m)[i]   != 0);
    else if (kind == 2) r = (((const float*)m)[i] != 0.f);
    else                r = (((const unsigned char*)m)[i] != 0);
    g_mask[i] = r;
}

// ===========================================================================
// HMMA GEMM NT (unchanged from R6, passing): C = A*B^T, bf16 hi/lo x3.
// ===========================================================================
#define GBM 128
#define GBN 128
#define GBK 32
#define GSTR 40
#define ARR_SZ (128 * GSTR * 2)
#define STAGE_SZ (4 * ARR_SZ)
#define GEMM_SMEM (2 * STAGE_SZ)
#define O_AH 0
#define O_AL ARR_SZ
#define O_BH (2 * ARR_SZ)
#define O_BL (3 * ARR_SZ)

extern __shared__ char sm_raw[];

template <int OUTMODE>
__global__ __launch_bounds__(256, 2) void gemm_bf16(
    const __nv_bfloat16* __restrict__ Agh, const __nv_bfloat16* __restrict__ Agl,
    const __nv_bfloat16* __restrict__ Bgh, const __nv_bfloat16* __restrict__ Bgl,
    float* __restrict__ Cf,
    __nv_bfloat16* __restrict__ Ch, __nv_bfloat16* __restrict__ Cl)
{
    uint32_t sb = smem_u32(sm_raw);
    const int tid = threadIdx.x;
    const int wid = tid >> 5;
    const int lane = tid & 31;
    const int wm = (wid & 1) * 64;
    const int wn = (wid >> 1) * 32;
    const size_t rowA0 = (size_t)blockIdx.y * GBM;
    const size_t rowB0 = (size_t)blockIdx.x * GBN;

    const int carr = tid >> 6;
    const int crow0 = (tid & 63) >> 1;
    const int cseg = (tid & 1) << 1;
    const __nv_bfloat16* gbase[4] = {
        Agh + rowA0 * EMB, Agl + rowA0 * EMB,
        Bgh + rowB0 * EMB, Bgl + rowB0 * EMB };
    const __nv_bfloat16* mygb = gbase[carr];
    const uint32_t myarr = sb + carr * ARR_SZ;

    float acc[4][4][4];
#pragma unroll
    for (int mt = 0; mt < 4; mt++)
#pragma unroll
        for (int nt = 0; nt < 4; nt++)
#pragma unroll
            for (int e = 0; e < 4; e++) acc[mt][nt][e] = 0.f;

    const int NCH = EMB / GBK;

#pragma unroll
    for (int rr = 0; rr < 4; rr++) {
        int row = crow0 + rr * 32;
        uint32_t smaddr = myarr + row * (GSTR * 2) + cseg * 16;
        const void* g = mygb + (size_t)row * EMB + cseg * 8;
        cp16(smaddr, g);
        cp16(smaddr + 16, (const char*)g + 16);
    }
    CP_COMMIT();

    for (int c = 0; c < NCH; c++) {
        const uint32_t stage = (uint32_t)(c & 1);
        if (c + 1 < NCH) {
            const int kt = (c + 1) * GBK;
            const uint32_t stb = myarr + ((c + 1) & 1) * STAGE_SZ;
#pragma unroll
            for (int rr = 0; rr < 4; rr++) {
                int row = crow0 + rr * 32;
                uint32_t smaddr = stb + row * (GSTR * 2) + cseg * 16;
                const void* g = mygb + (size_t)row * EMB + kt + cseg * 8;
                cp16(smaddr, g);
                cp16(smaddr + 16, (const char*)g + 16);
            }
            CP_COMMIT();
            CP_WAIT(1);
        } else {
            CP_WAIT(0);
        }
        __syncthreads();

        const uint32_t base = sb + stage * STAGE_SZ;
        const uint32_t lrow = lane & 15;
        const uint32_t lcol = (lane >> 4) << 3;
#pragma unroll
        for (int kk = 0; kk < GBK; kk += 16) {
            uint32_t af[4][4];
#pragma unroll
            for (int mt = 0; mt < 4; mt++) {
                uint32_t addr = base + O_AH +
                    (uint32_t)(((wm + mt * 16 + lrow) * GSTR + kk + lcol) * 2);
                ldsm_x4(af[mt], addr);
            }
            uint32_t b0h[4], b1h[4], b0l[4], b1l[4];
#pragma unroll
            for (int g = 0; g < 2; g++) {
                uint32_t roff = (uint32_t)(((wn + g * 16 + lrow) * GSTR + kk + lcol) * 2);
                uint32_t r4[4];
                ldsm_x4(r4, base + O_BH + roff);
                b0h[2 * g] = r4[0]; b0h[2 * g + 1] = r4[1];
                b1h[2 * g] = r4[2]; b1h[2 * g + 1] = r4[3];
                ldsm_x4(r4, base + O_BL + roff);
                b0l[2 * g] = r4[0]; b0l[2 * g + 1] = r4[1];
                b1l[2 * g] = r4[2]; b1l[2 * g + 1] = r4[3];
            }
#pragma unroll
            for (int mt = 0; mt < 4; mt++)
#pragma unroll
                for (int nt = 0; nt < 4; nt++) {
                    mma16816(acc[mt][nt], af[mt], b0h[nt], b1h[nt]);
                    mma16816(acc[mt][nt], af[mt], b0l[nt], b1l[nt]);
                }
#pragma unroll
            for (int mt = 0; mt < 4; mt++) {
                uint32_t addr = base + O_AL +
                    (uint32_t)(((wm + mt * 16 + lrow) * GSTR + kk + lcol) * 2);
                ldsm_x4(af[mt], addr);
            }
#pragma unroll
            for (int mt = 0; mt < 4; mt++)
#pragma unroll
                for (int nt = 0; nt < 4; nt++)
                    mma16816(acc[mt][nt], af[mt], b0h[nt], b1h[nt]);
        }
        __syncthreads();
    }

#pragma unroll
    for (int mt = 0; mt < 4; mt++) {
        size_t r0 = rowA0 + wm + mt * 16 + (lane >> 2);
        size_t r1 = r0 + 8;
#pragma unroll
        for (int nt = 0; nt < 4; nt++) {
            size_t cc = rowB0 + wn + nt * 8 + (lane & 3) * 2;
            if (OUTMODE == 0) {
                *(float2*)(Cf + r0 * EMB + cc) = make_float2(acc[mt][nt][0], acc[mt][nt][1]);
                *(float2*)(Cf + r1 * EMB + cc) = make_float2(acc[mt][nt][2], acc[mt][nt][3]);
            } else {
                __nv_bfloat16 h0, l0, h1, l1;
                split1(acc[mt][nt][0], h0, l0);
                split1(acc[mt][nt][1], h1, l1);
                *(uint32_t*)(Ch + r0 * EMB + cc) = pack2(h0, h1);
                *(uint32_t*)(Cl + r0 * EMB + cc) = pack2(l0, l1);
                split1(acc[mt][nt][2], h0, l0);
                split1(acc[mt][nt][3], h1, l1);
                *(uint32_t*)(Ch + r1 * EMB + cc) = pack2(h0, h1);
                *(uint32_t*)(Cl + r1 * EMB + cc) = pack2(l0, l1);
            }
        }
    }
}

// ===========================================================================
// FA2-style flash attention: 128 q/CTA, warp = 16q x 64k, register softmax,
// P register-resident (S c-frag == PV a-frag), cp.async double-buffered K/V.
// ===========================================================================
#define AQ 128
#define AK 64
#define ASTR 72
#define AROWB (ASTR * 2)       // 144 B per smem row
#define KVROWS (AK * AROWB)    // 9216 B per K/V array per stage

struct AttnSmem {
    __nv_bfloat16 Qh[AQ][ASTR], Ql[AQ][ASTR];       // 2 x 18432
    __nv_bfloat16 Kh[2][AK][ASTR], Kl[2][AK][ASTR]; // 4 x 9216
    __nv_bfloat16 Vh[2][AK][ASTR], Vl[2][AK][ASTR]; // 4 x 9216
    unsigned char msk[2][64];                       // 128
};
#define ATTN_SMEM ((int)sizeof(AttnSmem))

__global__ __launch_bounds__(256) void attn_mma(
    const __nv_bfloat16* __restrict__ Qhg, const __nv_bfloat16* __restrict__ Qlg,
    const __nv_bfloat16* __restrict__ Khg, const __nv_bfloat16* __restrict__ Klg,
    const __nv_bfloat16* __restrict__ Vhg, const __nv_bfloat16* __restrict__ Vlg,
    const unsigned char* __restrict__ mask,
    __nv_bfloat16* __restrict__ Ohg, __nv_bfloat16* __restrict__ Olg)
{
    AttnSmem& s = *reinterpret_cast<AttnSmem*>(sm_raw);
    const int b  = blockIdx.z;
    const int h  = blockIdx.y;
    const int qt = blockIdx.x;
    const int tid = threadIdx.x;
    const int wid = tid >> 5;
    const int lane = tid & 31;
    const size_t headoff = (size_t)h * HDIM;

    const uint32_t sqh = smem_u32(&s.Qh[0][0]);
    const uint32_t sql = smem_u32(&s.Ql[0][0]);
    const uint32_t skh = smem_u32(&s.Kh[0][0][0]);
    const uint32_t skl = smem_u32(&s.Kl[0][0][0]);
    const uint32_t svh = smem_u32(&s.Vh[0][0][0]);
    const uint32_t svl = smem_u32(&s.Vl[0][0][0]);
    const uint32_t smk = smem_u32(&s.msk[0][0]);

    // --- Q tile load: 128 x 64 hi/lo, 16B vector loads ---
#pragma unroll
    for (int t = 0; t < 4; t++) {
        int i = tid + t * 256;            // 0..1023
        int r = i >> 3, seg = i & 7;      // row, 16B segment
        size_t gi = ((size_t)(qt * AQ + r) * BATCH + b) * EMB + headoff + seg * 8;
        *(uint4*)((char*)&s.Qh[r][0] + seg * 16) = *(const uint4*)(Qhg + gi);
        *(uint4*)((char*)&s.Ql[r][0] + seg * 16) = *(const uint4*)(Qlg + gi);
    }

    // --- cp.async assignment: tid>>6 -> array, tid&63 -> row (8 x 16B) ---
    const int ca = tid >> 6;
    const int crow = tid & 63;
    const __nv_bfloat16* casrc = (ca == 0) ? Khg : (ca == 1) ? Klg
                                : (ca == 2) ? Vhg : Vlg;
    const uint32_t cadst = (ca == 0) ? skh : (ca == 1) ? skl
                          : (ca == 2) ? svh : svl;

    // prefetch k-tile 0 into stage 0
    {
        size_t gi = ((size_t)crow * BATCH + b) * EMB + headoff;
        const char* g = (const char*)(casrc + gi);
        uint32_t d = cadst + crow * AROWB;
#pragma unroll
        for (int seg = 0; seg < 8; seg++) cp16(d + seg * 16, g + seg * 16);
        if (tid < 4) cp16(smk + tid * 16, mask + (size_t)b * T_K + tid * 16);
    }
    CP_COMMIT();

    float m0 = -INFINITY, m1 = -INFINITY, l0 = 0.f, l1 = 0.f;
    float o[8][4];
#pragma unroll
    for (int nt = 0; nt < 8; nt++)
#pragma unroll
        for (int e = 0; e < 4; e++) o[nt][e] = 0.f;

    const uint32_t lrow = lane & 15;
    const uint32_t lcol = (lane >> 4) << 3;
    const int NT = T_K / AK;     // 32

    for (int kt = 0; kt < NT; kt++) {
        if (kt + 1 < NT) {
            int st2 = (kt + 1) & 1;
            size_t gi = ((size_t)((kt + 1) * AK + crow) * BATCH + b) * EMB + headoff;
            const char* g = (const char*)(casrc + gi);
            uint32_t d = cadst + st2 * KVROWS + crow * AROWB;
#pragma unroll
            for (int seg = 0; seg < 8; seg++) cp16(d + seg * 16, g + seg * 16);
            if (tid < 4)
                cp16(smk + st2 * 64 + tid * 16,
                     mask + (size_t)b * T_K + (kt + 1) * AK + tid * 16);
            CP_COMMIT();
            CP_WAIT(1);
        } else {
            CP_WAIT(0);
        }
        __syncthreads();

        const int st = kt & 1;
        const uint32_t kbh = skh + st * KVROWS;
        const uint32_t kbl = skl + st * KVROWS;
        const uint32_t vbh = svh + st * KVROWS;
        const uint32_t vbl = svl + st * KVROWS;
        const unsigned char* mrow = &s.msk[st][0];

        // ---- S = Q K^T (warp: 16q x 64k), 3 chains ----
        float sc[8][4];
#pragma unroll
        for (int nt = 0; nt < 8; nt++)
#pragma unroll
            for (int e = 0; e < 4; e++) sc[nt][e] = 0.f;

#pragma unroll
        for (int kk = 0; kk < 4; kk++) {
            uint32_t aoff = (uint32_t)(((wid * 16 + lrow) * ASTR + kk * 16 + lcol) * 2);
            uint32_t ah[4], al[4];
            ldsm_x4(ah, sqh + aoff);
            ldsm_x4(al, sql + aoff);
            uint32_t b0h[8], b1h[8], b0l[8], b1l[8];
#pragma unroll
            for (int g = 0; g < 4; g++) {
                uint32_t roff = (uint32_t)(((g * 16 + lrow) * ASTR + kk * 16 + lcol) * 2);
                uint32_t r4[4];
                ldsm_x4(r4, kbh + roff);
                b0h[2*g] = r4[0]; b0h[2*g+1] = r4[1];
                b1h[2*g] = r4[2]; b1h[2*g+1] = r4[3];
                ldsm_x4(r4, kbl + roff);
                b0l[2*g] = r4[0]; b0l[2*g+1] = r4[1];
                b1l[2*g] = r4[2]; b1l[2*g+1] = r4[3];
            }
#pragma unroll
            for (int nt = 0; nt < 8; nt++) {
                mma16816(sc[nt], ah, b0h[nt], b1h[nt]);
                mma16816(sc[nt], ah, b0l[nt], b1l[nt]);
                mma16816(sc[nt], al, b0h[nt], b1h[nt]);
            }
        }

        // ---- register softmax ----
        float tm0 = -INFINITY, tm1 = -INFINITY;
#pragma unroll
        for (int nt = 0; nt < 8; nt++) {
            int k0 = nt * 8 + (lane & 3) * 2;
            bool mk0 = mrow[k0] != 0, mk1 = mrow[k0 + 1] != 0;
            sc[nt][0] = mk0 ? NEGINF : sc[nt][0] * 0.125f;
            sc[nt][1] = mk1 ? NEGINF : sc[nt][1] * 0.125f;
            sc[nt][2] = mk0 ? NEGINF : sc[nt][2] * 0.125f;
            sc[nt][3] = mk1 ? NEGINF : sc[nt][3] * 0.125f;
            tm0 = fmaxf(tm0, fmaxf(sc[nt][0], sc[nt][1]));
            tm1 = fmaxf(tm1, fmaxf(sc[nt][2], sc[nt][3]));
        }
        tm0 = fmaxf(tm0, __shfl_xor_sync(0xffffffffu, tm0, 1));
        tm0 = fmaxf(tm0, __shfl_xor_sync(0xffffffffu, tm0, 2));
        tm1 = fmaxf(tm1, __shfl_xor_sync(0xffffffffu, tm1, 1));
        tm1 = fmaxf(tm1, __shfl_xor_sync(0xffffffffu, tm1, 2));

        float mn0 = fmaxf(m0, tm0), mn1 = fmaxf(m1, tm1);
        float al0 = __expf(m0 - mn0), al1 = __expf(m1 - mn1);
        m0 = mn0; m1 = mn1;

        float ts0 = 0.f, ts1 = 0.f;
        uint32_t pfh[4][4], pfl[4][4];
#pragma unroll
        for (int nt = 0; nt < 8; nt++) {
            float p0 = __expf(sc[nt][0] - mn0);
            float p1 = __expf(sc[nt][1] - mn0);
            float p2 = __expf(sc[nt][2] - mn1);
            float p3 = __expf(sc[nt][3] - mn1);
            ts0 += p0 + p1;
            ts1 += p2 + p3;
            __nv_bfloat16 h0, lo0, h1, lo1;
            int t = nt >> 1, half = (nt & 1) * 2;
            split1(p0, h0, lo0); split1(p1, h1, lo1);
            pfh[t][half + 0] = pack2(h0, h1);
            pfl[t][half + 0] = pack2(lo0, lo1);
            split1(p2, h0, lo0); split1(p3, h1, lo1);
            pfh[t][half + 1] = pack2(h0, h1);
            pfl[t][half + 1] = pack2(lo0, lo1);
        }
        ts0 += __shfl_xor_sync(0xffffffffu, ts0, 1);
        ts0 += __shfl_xor_sync(0xffffffffu, ts0, 2);
        ts1 += __shfl_xor_sync(0xffffffffu, ts1, 1);
        ts1 += __shfl_xor_sync(0xffffffffu, ts1, 2);
        l0 = l0 * al0 + ts0;
        l1 = l1 * al1 + ts1;

#pragma unroll
        for (int nt = 0; nt < 8; nt++) {
            o[nt][0] *= al0; o[nt][1] *= al0;
            o[nt][2] *= al1; o[nt][3] *= al1;
        }

        // ---- O += P V (warp: 16q x 64d), 3 chains ----
#pragma unroll
        for (int t = 0; t < 4; t++) {
            uint32_t b0h[8], b1h[8], b0l[8], b1l[8];
#pragma unroll
            for (int g = 0; g < 4; g++) {
                uint32_t vrow = (uint32_t)(t * 16 + (lane & 7) + ((lane >> 3) & 1) * 8);
                uint32_t vcol = (uint32_t)(g * 16 + ((lane >> 4) << 3));
                uint32_t roff = (vrow * ASTR + vcol) * 2;
                uint32_t r4[4];
                ldsm_x4_t(r4, vbh + roff);
                b0h[2*g] = r4[0]; b1h[2*g] = r4[1];
                b0h[2*g+1] = r4[2]; b1h[2*g+1] = r4[3];
                ldsm_x4_t(r4, vbl + roff);
                b0l[2*g] = r4[0]; b1l[2*g] = r4[1];
                b0l[2*g+1] = r4[2]; b1l[2*g+1] = r4[3];
            }
#pragma unroll
            for (int nt = 0; nt < 8; nt++) {
                mma16816(o[nt], pfh[t], b0h[nt], b1h[nt]);
                mma16816(o[nt], pfh[t], b0l[nt], b1l[nt]);
                mma16816(o[nt], pfl[t], b0h[nt], b1h[nt]);
            }
        }
        __syncthreads();
    }

    // ---- finalize: /l, write bf16 hi/lo AO at (t, b, e) ----
    float inv0 = 1.f / l0;
    float inv1 = 1.f / l1;
    const int r0 = wid * 16 + (lane >> 2);
    const int r1 = r0 + 8;
    size_t tg0 = (size_t)(qt * AQ + r0) * BATCH + b;
    size_t tg1 = (size_t)(qt * AQ + r1) * BATCH + b;
#pragma unroll
    for (int nt = 0; nt < 8; nt++) {
        size_t d0 = nt * 8 + (lane & 3) * 2;
        __nv_bfloat16 h0, lo0, h1, lo1;
        split1(o[nt][0] * inv0, h0, lo0);
        split1(o[nt][1] * inv0, h1, lo1);
        *(uint32_t*)(Ohg + tg0 * EMB + headoff + d0) = pack2(h0, h1);
        *(uint32_t*)(Olg + tg0 * EMB + headoff + d0) = pack2(lo0, lo1);
        split1(o[nt][2] * inv1, h0, lo0);
        split1(o[nt][3] * inv1, h1, lo1);
        *(uint32_t*)(Ohg + tg1 * EMB + headoff + d0) = pack2(h0, h1);
        *(uint32_t*)(Olg + tg1 * EMB + headoff + d0) = pack2(lo0, lo1);
    }
}

// ===========================================================================
// Launch
// ===========================================================================
extern "C" void kernel_launch(void* const* d_in, const int* in_sizes, int n_in,
                              void* d_out, int out_size)
{
    const float* q  = (const float*)d_in[0];
    const float* k  = (const float*)d_in[1];
    const float* v  = (const float*)d_in[2];
    const void*  maskraw = d_in[3];
    const float* Wq = (const float*)d_in[4];
    const float* Wk = (const float*)d_in[5];
    const float* Wv = (const float*)d_in[6];
    const float* Wo = (const float*)d_in[7];
    float* out = (float*)d_out;

    __nv_bfloat16 *qh, *ql, *kh, *kl, *vh, *vl;
    __nv_bfloat16 *wqh, *wql, *wkh, *wkl, *wvh, *wvl, *woh, *wol;
    __nv_bfloat16 *pqh, *pql, *pkh, *pkl, *pvh, *pvl, *aoh, *aol;
    unsigned char* gmask;
    cudaGetSymbolAddress((void**)&qh, c_qh);  cudaGetSymbolAddress((void**)&ql, c_ql);
    cudaGetSymbolAddress((void**)&kh, c_kh);  cudaGetSymbolAddress((void**)&kl, c_kl);
    cudaGetSymbolAddress((void**)&vh, c_vh);  cudaGetSymbolAddress((void**)&vl, c_vl);
    cudaGetSymbolAddress((void**)&wqh, c_wqh); cudaGetSymbolAddress((void**)&wql, c_wql);
    cudaGetSymbolAddress((void**)&wkh, c_wkh); cudaGetSymbolAddress((void**)&wkl, c_wkl);
    cudaGetSymbolAddress((void**)&wvh, c_wvh); cudaGetSymbolAddress((void**)&wvl, c_wvl);
    cudaGetSymbolAddress((void**)&woh, c_woh); cudaGetSymbolAddress((void**)&wol, c_wol);
    cudaGetSymbolAddress((void**)&pqh, p_qh);  cudaGetSymbolAddress((void**)&pql, p_ql);
    cudaGetSymbolAddress((void**)&pkh, p_kh);  cudaGetSymbolAddress((void**)&pkl, p_kl);
    cudaGetSymbolAddress((void**)&pvh, p_vh);  cudaGetSymbolAddress((void**)&pvl, p_vl);
    cudaGetSymbolAddress((void**)&aoh, ao_h);  cudaGetSymbolAddress((void**)&aol, ao_l);
    cudaGetSymbolAddress((void**)&gmask, g_mask);

    cudaFuncSetAttribute(attn_mma, cudaFuncAttributeMaxDynamicSharedMemorySize,
                         ATTN_SMEM);
    cudaFuncSetAttribute(gemm_bf16<0>, cudaFuncAttributeMaxDynamicSharedMemorySize,
                         GEMM_SMEM);
    cudaFuncSetAttribute(gemm_bf16<1>, cudaFuncAttributeMaxDynamicSharedMemorySize,
                         GEMM_SMEM);

    sniff_mask_kernel<<<1, 256>>>((const unsigned char*)maskraw);
    norm_mask_kernel<<<NMASK / 256, 256>>>(maskraw);

    const int NIN = MROWS * EMB;
    const int NW  = EMB * EMB;
    conv_qkv<<<dim3(NIN / 4 / 256, 3), 256>>>(q, k, v, qh, ql, kh, kl, vh, vl);
    conv_w<<<dim3(NW / 4 / 256, 4), 256>>>(Wq, Wk, Wv, Wo,
                                           wqh, wql, wkh, wkl,
                                           wvh, wvl, woh, wol);

    dim3 ggrid(EMB / GBN, MROWS / GBM);   // (8, 64)
    gemm_bf16<1><<<ggrid, 256, GEMM_SMEM>>>(qh, ql, wqh, wql, nullptr, pqh, pql);
    gemm_bf16<1><<<ggrid, 256, GEMM_SMEM>>>(kh, kl, wkh, wkl, nullptr, pkh, pkl);
    gemm_bf16<1><<<ggrid, 256, GEMM_SMEM>>>(vh, vl, wvh, wvl, nullptr, pvh, pvl);

    dim3 agrid(T_Q / AQ, NHEADS, BATCH);  // (16, 16, 4)
    attn_mma<<<agrid, 256, ATTN_SMEM>>>(pqh, pql, pkh, pkl, pvh, pvl, gmask,
                                        aoh, aol);

    gemm_bf16<0><<<ggrid, 256, GEMM_SMEM>>>(aoh, aol, woh, wol, out,
                                            nullptr, nullptr);
}